// round 16
// baseline (speedup 1.0000x reference)
#include <cuda_runtime.h>
#include <cuda_bf16.h>
#include <cuda_fp16.h>
#include <cstdint>

// Problem constants
#define B_    2
#define TQ_   1024
#define DIN_  4096
#define H_    32
#define G_    8
#define HD_   128
#define SPREV 1024
#define SKV   2048          // SPREV + TQ
#define BT_   (B_*TQ_)      // 2048
#define NQKV  6144          // H*HD + 2*G*HD

// ---------------- scratch (no allocation allowed -> __device__ globals) ---------
__device__ __half g_xh  [(size_t)BT_ * DIN_];        // fp16 x
__device__ __half g_wqkvh[(size_t)NQKV * DIN_];      // fp16 [Wq;Wk;Wv]
__device__ __half g_woh [(size_t)DIN_ * H_ * HD_];   // fp16 Wo
__device__ __half g_qh  [(size_t)BT_ * H_ * HD_];    // fp16 Q (post norm+rope)
__device__ __half g_ctxh[(size_t)BT_ * H_ * HD_];    // fp16 attention output
__device__ __half g_kh  [(size_t)B_ * G_ * SKV * HD_]; // fp16 mirror of k_all
__device__ __half g_vh  [(size_t)B_ * G_ * SKV * HD_]; // fp16 mirror of v_all

// =============================================================================
// helpers
// =============================================================================
__device__ __forceinline__ void cp16(void* s, const void* g){
    unsigned sa = (unsigned)__cvta_generic_to_shared(s);
    asm volatile("cp.async.cg.shared.global [%0], [%1], 16;\n" :: "r"(sa), "l"(g));
}
__device__ __forceinline__ void cp_commit(){ asm volatile("cp.async.commit_group;\n" ::); }
template<int NN> __device__ __forceinline__ void cp_wait(){
    asm volatile("cp.async.wait_group %0;\n" :: "n"(NN));
}
__device__ __forceinline__ void mma_f16(float* c, const unsigned* a, const unsigned* b){
    asm volatile(
      "mma.sync.aligned.m16n8k16.row.col.f32.f16.f16.f32 "
      "{%0,%1,%2,%3}, {%4,%5,%6,%7}, {%8,%9}, {%0,%1,%2,%3};"
      : "+f"(c[0]), "+f"(c[1]), "+f"(c[2]), "+f"(c[3])
      : "r"(a[0]), "r"(a[1]), "r"(a[2]), "r"(a[3]), "r"(b[0]), "r"(b[1]));
}
__device__ __forceinline__ void ldsm_x4(unsigned& r0, unsigned& r1,
                                        unsigned& r2, unsigned& r3,
                                        const void* p){
    unsigned sa = (unsigned)__cvta_generic_to_shared(p);
    asm volatile("ldmatrix.sync.aligned.m8n8.x4.shared.b16 {%0,%1,%2,%3}, [%4];"
                 : "=r"(r0), "=r"(r1), "=r"(r2), "=r"(r3) : "r"(sa));
}
__device__ __forceinline__ void ldsm_x4_trans(unsigned& r0, unsigned& r1,
                                              unsigned& r2, unsigned& r3,
                                              const void* p){
    unsigned sa = (unsigned)__cvta_generic_to_shared(p);
    asm volatile("ldmatrix.sync.aligned.m8n8.x4.trans.shared.b16 {%0,%1,%2,%3}, [%4];"
                 : "=r"(r0), "=r"(r1), "=r"(r2), "=r"(r3) : "r"(sa));
}

// =============================================================================
// fused fp32 -> fp16 convert pre-pass (x, Wq, Wk, Wv, Wo in one launch)
// =============================================================================
__global__ void to_half_all(const float4* __restrict__ x,  const float4* __restrict__ wq,
                            const float4* __restrict__ wk, const float4* __restrict__ wv,
                            const float4* __restrict__ wo)
{
    size_t i = (size_t)blockIdx.x * 256 + threadIdx.x;      // 12,582,912 float4s
    const float4* s; __half* d; size_t off;
    if      (i <  2097152u) { s = x;  d = g_xh;              off = i; }
    else if (i <  6291456u) { s = wq; d = g_wqkvh;           off = i - 2097152u; }
    else if (i <  7340032u) { s = wk; d = g_wqkvh + 16777216; off = i - 6291456u; }
    else if (i <  8388608u) { s = wv; d = g_wqkvh + 20971520; off = i - 7340032u; }
    else                    { s = wo; d = g_woh;             off = i - 8388608u; }
    float4 v = s[off];
    __half2 h0 = __floats2half2_rn(v.x, v.y);
    __half2 h1 = __floats2half2_rn(v.z, v.w);
    uint2 u; u.x = *(unsigned*)&h0; u.y = *(unsigned*)&h1;
    ((uint2*)d)[off] = u;
}

// =============================================================================
// GEMM common: 128x128x64 fp16 mainloop macro bits
// =============================================================================
#define HP 72                        // smem pitch (halves)
#define HBK 64                       // k per stage (halves)
#define GEMM_SMEM_H (2 * 128 * HP * 2 * 2)   // 73728 B

#define GEMM_MAINLOOP(Ag, Bg, K)                                              \
    float c[4][8][4];                                                         \
    _Pragma("unroll")                                                         \
    for (int i = 0; i < 4; i++)                                               \
        _Pragma("unroll")                                                     \
        for (int j = 0; j < 8; j++)                                           \
            _Pragma("unroll")                                                 \
            for (int t = 0; t < 4; t++) c[i][j][t] = 0.f;                     \
    const int nkt = (K) / HBK;                                                \
    HSTAGE(0, 0); cp_commit();                                                \
    const int a_roff = (sel & 1) * 8 + lr;                                    \
    const int a_coff = (sel >> 1) * 8;                                        \
    const int b_toff = (sel >> 1);                                            \
    const int b_coff = (sel & 1) * 8;                                         \
    for (int kt = 0; kt < nkt; kt++) {                                        \
        if (kt + 1 < nkt) { HSTAGE((kt + 1) & 1, kt + 1); cp_commit(); cp_wait<1>(); } \
        else              { cp_wait<0>(); }                                   \
        __syncthreads();                                                      \
        const __half* Ab = As + (kt & 1) * 128 * HP;                          \
        const __half* Bb = Bs + (kt & 1) * 128 * HP;                          \
        _Pragma("unroll")                                                     \
        for (int ks = 0; ks < 4; ks++) {                                      \
            const int kch = ks * 16;                                          \
            unsigned a[4][4], bfr[8][2];                                      \
            _Pragma("unroll")                                                 \
            for (int f = 0; f < 4; f++)                                       \
                ldsm_x4(a[f][0], a[f][1], a[f][2], a[f][3],                   \
                        Ab + (wm + f * 16 + a_roff) * HP + kch + a_coff);     \
            _Pragma("unroll")                                                 \
            for (int jj = 0; jj < 4; jj++)                                    \
                ldsm_x4(bfr[2*jj][0], bfr[2*jj][1], bfr[2*jj+1][0], bfr[2*jj+1][1], \
                        Bb + (wn + (2*jj + b_toff) * 8 + lr) * HP + kch + b_coff);  \
            _Pragma("unroll")                                                 \
            for (int i = 0; i < 4; i++)                                       \
                _Pragma("unroll")                                             \
                for (int j = 0; j < 8; j++)                                   \
                    mma_f16(c[i][j], a[i], bfr[j]);                           \
        }                                                                     \
        __syncthreads();                                                      \
    }

#define HSTAGE(buf, kt) do {                                                 \
    __half* da = As + (buf) * 128 * HP;                                      \
    __half* db = Bs + (buf) * 128 * HP;                                      \
    const __half* sa = Ag + (size_t)(kt) * HBK;                              \
    const __half* sb = Bg + (size_t)(kt) * HBK;                              \
    _Pragma("unroll")                                                        \
    for (int i = 0; i < 8; i++){                                             \
        int idx = i * 128 + tid; int row = idx >> 3; int sg = (idx & 7) * 8; \
        cp16(da + row * HP + sg, sa + (size_t)row * K + sg);                 \
        cp16(db + row * HP + sg, sb + (size_t)row * K + sg);                 \
    }                                                                        \
} while (0)

// =============================================================================
// Plain fp16 GEMM (used for the output projection): C fp32, plain store.
// =============================================================================
__global__ void __launch_bounds__(128) gemm_fp16(const __half* __restrict__ A,
                                                 const __half* __restrict__ Bm,
                                                 float* __restrict__ C,
                                                 int M, int N, int K)
{
    extern __shared__ __half shh[];
    __half* As = shh;
    __half* Bs = shh + 2 * 128 * HP;

    const int tid  = threadIdx.x;
    const int lane = tid & 31, warp = tid >> 5;
    const int g  = lane >> 2, tg = lane & 3;
    const int wm = (warp >> 1) * 64, wn = (warp & 1) * 64;
    const int lr  = lane & 7;
    const int sel = lane >> 3;

    const __half* Ag = A  + (size_t)blockIdx.y * 128 * K;
    const __half* Bg = Bm + (size_t)blockIdx.x * 128 * K;

    GEMM_MAINLOOP(Ag, Bg, K)

    #pragma unroll
    for (int i = 0; i < 4; i++) {
        int row0 = blockIdx.y * 128 + wm + i * 16 + g;
        #pragma unroll
        for (int j = 0; j < 8; j++) {
            int col = blockIdx.x * 128 + wn + j * 8 + 2 * tg;
            *(float2*)(C + (size_t)row0 * N + col)       = make_float2(c[i][j][0], c[i][j][1]);
            *(float2*)(C + (size_t)(row0 + 8) * N + col) = make_float2(c[i][j][2], c[i][j][3]);
        }
    }
}

// =============================================================================
// Fused QKV GEMM: [2048 x 6144] = xh @ [Wq;Wk;Wv]^T with rmsnorm+rope+scatter
// epilogue. Column tile bx: 0..31 = Q head bx, 32..39 = K group bx-32,
// 40..47 = V group bx-40. Each CTA tile = 128 tokens x 1 full head (128 dims).
// Epilogue: accum -> smem 128x130 fp32 (pitch EVEN -> float2 stores 8B-aligned;
// 130 == 2 mod 32 -> only 2-way read conflict) -> per-token norm/rope -> sinks.
// =============================================================================
#define CP_ 130
__global__ void __launch_bounds__(128) gemm_qkv_fused(
        const __half* __restrict__ A, const __half* __restrict__ Bm,
        __half* __restrict__ qh,
        float* __restrict__ kall, __half* __restrict__ kh,
        float* __restrict__ vall, __half* __restrict__ vh,
        const float* __restrict__ qw, const float* __restrict__ kw,
        const float* __restrict__ cosT, const float* __restrict__ sinT,
        const int* __restrict__ pid)
{
    extern __shared__ __half shh[];
    __half* As = shh;
    __half* Bs = shh + 2 * 128 * HP;
    const int K = DIN_;

    const int tid  = threadIdx.x;
    const int lane = tid & 31, warp = tid >> 5;
    const int g  = lane >> 2, tg = lane & 3;
    const int wm = (warp >> 1) * 64, wn = (warp & 1) * 64;
    const int lr  = lane & 7;
    const int sel = lane >> 3;

    const __half* Ag = A  + (size_t)blockIdx.y * 128 * K;
    const __half* Bg = Bm + (size_t)blockIdx.x * 128 * K;

    GEMM_MAINLOOP(Ag, Bg, K)

    // ---- epilogue: dump accumulators to fp32 smem tile (pitch 130, even) ----
    float* Cs = (float*)shh;                    // 128 x 130 = 66560 B <= 73728
    #pragma unroll
    for (int i = 0; i < 4; i++) {
        int r0 = wm + i * 16 + g;
        #pragma unroll
        for (int j = 0; j < 8; j++) {
            int col = wn + j * 8 + 2 * tg;
            *(float2*)(Cs + r0 * CP_ + col)       = make_float2(c[i][j][0], c[i][j][1]);
            *(float2*)(Cs + (r0 + 8) * CP_ + col) = make_float2(c[i][j][2], c[i][j][3]);
        }
    }
    __syncthreads();

    const int row = tid;                        // token-row within tile
    const int bt  = blockIdx.y * 128 + row;
    const int bx  = blockIdx.x;
    const float* cr = Cs + row * CP_;
    const int b = bt >> 10, t = bt & 1023;

    if (bx < 32) {
        // ---- Q: rmsnorm + rope -> fp16 g_qh ----
        const int pos = pid[bt];
        float ss = 0.f;
        #pragma unroll 8
        for (int d = 0; d < 128; d++) { float xv = cr[d]; ss += xv * xv; }
        float rinv = rsqrtf(ss * (1.f / 128.f) + 1e-6f);
        const float* cf = cosT + (size_t)pos * 128;
        const float* sf = sinT + (size_t)pos * 128;
        unsigned qlo[32], qhi[32];
        #pragma unroll
        for (int d2 = 0; d2 < 32; d2++) {
            int d = 2 * d2;
            float x0 = cr[d]      * rinv * qw[d];
            float x1 = cr[d + 1]  * rinv * qw[d + 1];
            float y0 = cr[d + 64] * rinv * qw[d + 64];
            float y1 = cr[d + 65] * rinv * qw[d + 65];
            __half2 hlo = __floats2half2_rn(x0 * cf[d]      - y0 * sf[d],
                                            x1 * cf[d + 1]  - y1 * sf[d + 1]);
            __half2 hhi = __floats2half2_rn(y0 * cf[d + 64] + x0 * sf[d + 64],
                                            y1 * cf[d + 65] + x1 * sf[d + 65]);
            qlo[d2] = *(unsigned*)&hlo;
            qhi[d2] = *(unsigned*)&hhi;
        }
        __half* dst = qh + (size_t)bt * (H_ * HD_) + bx * HD_;
        #pragma unroll
        for (int kk = 0; kk < 8; kk++) {
            uint4 u; u.x = qlo[4*kk]; u.y = qlo[4*kk+1]; u.z = qlo[4*kk+2]; u.w = qlo[4*kk+3];
            *(uint4*)(dst + kk * 8) = u;
            uint4 v; v.x = qhi[4*kk]; v.y = qhi[4*kk+1]; v.z = qhi[4*kk+2]; v.w = qhi[4*kk+3];
            *(uint4*)(dst + 64 + kk * 8) = v;
        }
    } else if (bx < 40) {
        // ---- K: rmsnorm + rope -> fp32 kall (output) + fp16 mirror ----
        const int pos = pid[bt];
        const int gk = bx - 32;
        float ss = 0.f;
        #pragma unroll 8
        for (int d = 0; d < 128; d++) { float xv = cr[d]; ss += xv * xv; }
        float rinv = rsqrtf(ss * (1.f / 128.f) + 1e-6f);
        const float* cf = cosT + (size_t)pos * 128;
        const float* sf = sinT + (size_t)pos * 128;
        size_t ro = (((size_t)(b * G_ + gk) * SKV) + SPREV + t) * HD_;
        float* dk = kall + ro;
        __half* dh = kh + ro;
        #pragma unroll
        for (int d2 = 0; d2 < 32; d2++) {
            int d = 2 * d2;
            float x0 = cr[d]      * rinv * kw[d];
            float x1 = cr[d + 1]  * rinv * kw[d + 1];
            float y0 = cr[d + 64] * rinv * kw[d + 64];
            float y1 = cr[d + 65] * rinv * kw[d + 65];
            float o0 = x0 * cf[d]      - y0 * sf[d];
            float o1 = x1 * cf[d + 1]  - y1 * sf[d + 1];
            float p0 = y0 * cf[d + 64] + x0 * sf[d + 64];
            float p1 = y1 * cf[d + 65] + x1 * sf[d + 65];
            *(float2*)(dk + d)      = make_float2(o0, o1);
            *(float2*)(dk + 64 + d) = make_float2(p0, p1);
            __half2 hlo = __floats2half2_rn(o0, o1);
            __half2 hhi = __floats2half2_rn(p0, p1);
            *(__half2*)(dh + d)      = hlo;
            *(__half2*)(dh + 64 + d) = hhi;
        }
    } else {
        // ---- V: straight fp32 + fp16 scatter ----
        const int gv = bx - 40;
        size_t ro = (((size_t)(b * G_ + gv) * SKV) + SPREV + t) * HD_;
        float* dv = vall + ro;
        __half* dh = vh + ro;
        #pragma unroll
        for (int c4 = 0; c4 < 128; c4 += 4) {
            float4 v = make_float4(cr[c4], cr[c4+1], cr[c4+2], cr[c4+3]);
            *(float4*)(dv + c4) = v;
            __half2 h0 = __floats2half2_rn(v.x, v.y);
            __half2 h1 = __floats2half2_rn(v.z, v.w);
            uint2 u; u.x = *(unsigned*)&h0; u.y = *(unsigned*)&h1;
            *(uint2*)(dh + c4) = u;
        }
    }
}

// =============================================================================
// prev_k/prev_v -> fp32 caches + fp16 mirrors
// =============================================================================
__global__ void prev_scatter(const float* __restrict__ pk, const float* __restrict__ pv,
                             float* __restrict__ kall, float* __restrict__ vall,
                             __half* __restrict__ kh, __half* __restrict__ vh)
{
    size_t i = (size_t)blockIdx.x * blockDim.x + threadIdx.x;  // 524288 float4s
    int d4 = i & 31;
    int s  = (i >> 5) & 1023;
    int bg = (int)(i >> 15);
    size_t dst = ((size_t)bg * SKV + s) * 32 + d4;
    float4 k = ((const float4*)pk)[i];
    float4 v = ((const float4*)pv)[i];
    ((float4*)kall)[dst] = k;
    ((float4*)vall)[dst] = v;
    __half2 a0 = __floats2half2_rn(k.x, k.y), a1 = __floats2half2_rn(k.z, k.w);
    __half2 b0 = __floats2half2_rn(v.x, v.y), b1 = __floats2half2_rn(v.z, v.w);
    uint2 uk; uk.x = *(unsigned*)&a0; uk.y = *(unsigned*)&a1;
    uint2 uv; uv.x = *(unsigned*)&b0; uv.y = *(unsigned*)&b1;
    ((uint2*)kh)[dst] = uk;
    ((uint2*)vh)[dst] = uv;
}

// =============================================================================
// Full-fp16 tensor-core flash attention (m16n8k16, fp32 accum).
// Block 256 threads (8 warps) = (b, h, 128-query tile); KV tile = 64.
// K/V read from fp16 mirrors via cp.async; ldmatrix everywhere.
// Smem (half): Qs 128x136, Ks 64x136, Vs 64x136, Ps 128x72. 88064 B -> 2 CTAs/SM.
// =============================================================================
#define ATTN_SMEM 88064

__global__ void __launch_bounds__(256, 2) attn_tc(const __half* __restrict__ qh,
                                                  const __half* __restrict__ kh,
                                                  const __half* __restrict__ vh,
                                                  __half* __restrict__ ctxh)
{
    extern __shared__ char smraw[];
    __half* Qs  = (__half*)smraw;                     // 128 x 136
    __half* Ks  = (__half*)(smraw + 34816);           // 64 x 136
    __half* Vs  = (__half*)(smraw + 52224);           // 64 x 136 (row-major [k][n])
    __half* PsH = (__half*)(smraw + 69632);           // 128 x 72

    const int t0 = blockIdx.x * 128;
    const int h  = blockIdx.y;
    const int b  = blockIdx.z;
    const int gk = h >> 2;             // kv group (H/G = 4)
    const int tid = threadIdx.x;
    const int lane = tid & 31, w = tid >> 5;
    const int g = lane >> 2, tg = lane & 3;
    const int lr  = lane & 7;
    const int sel = lane >> 3;

    // Q tile (fp16, rows stride H*HD)
    const __half* qbase = qh + (size_t)(b * TQ_ + t0) * (H_ * HD_) + h * HD_;
    #pragma unroll 4
    for (int i = tid; i < 128 * 16; i += 256) {
        int row = i >> 4, c8 = (i & 15) * 8;
        *(uint4*)(Qs + row * 136 + c8) =
            *(const uint4*)(qbase + (size_t)row * (H_ * HD_) + c8);
    }

    const int row0 = 16 * w + g;
    const int qp0 = SPREV + t0 + row0;
    const int qp1 = qp0 + 8;
    const int kv_lim = SPREV + t0 + 128;
    const float scale = 0.08838834764831845f;    // 1/sqrt(128)

    const int a_roff = (sel & 1) * 8 + lr;
    const int a_coff = (sel >> 1) * 8;
    const int b_toff = (sel >> 1);
    const int b_coff = (sel & 1) * 8;
    const int vrow_l = lane & 15;
    const int vcol_l = (lane >> 4) << 3;

    const __half* kb = kh + (size_t)(b * G_ + gk) * SKV * HD_;
    const __half* vb = vh + (size_t)(b * G_ + gk) * SKV * HD_;

    float oacc[16][4];
    #pragma unroll
    for (int j = 0; j < 16; j++)
        #pragma unroll
        for (int t = 0; t < 4; t++) oacc[j][t] = 0.f;
    float m0 = -1e30f, m1 = -1e30f, l0 = 0.f, l1 = 0.f;

    __syncthreads();

    for (int j0 = 0; j0 < kv_lim; j0 += 64) {
        // K,V tiles via cp.async (fp16 source, straight copy)
        #pragma unroll
        for (int i = tid; i < 64 * 16; i += 256) {
            int row = i >> 4, sg = (i & 15) * 8;
            cp16(Ks + row * 136 + sg, kb + (size_t)(j0 + row) * HD_ + sg);
            cp16(Vs + row * 136 + sg, vb + (size_t)(j0 + row) * HD_ + sg);
        }
        cp_commit();
        cp_wait<0>();
        __syncthreads();

        // ---- S = Q K^T  (fp16 m16n8k16, 8 k-steps, ldmatrix frags) ----
        float sacc[8][4];
        #pragma unroll
        for (int j = 0; j < 8; j++)
            #pragma unroll
            for (int t = 0; t < 4; t++) sacc[j][t] = 0.f;

        #pragma unroll
        for (int ks = 0; ks < 8; ks++) {
            const int kch = ks * 16;
            unsigned a[4];
            ldsm_x4(a[0], a[1], a[2], a[3],
                    Qs + (16 * w + a_roff) * 136 + kch + a_coff);
            unsigned bb[8][2];
            #pragma unroll
            for (int jj = 0; jj < 4; jj++)
                ldsm_x4(bb[2*jj][0], bb[2*jj][1], bb[2*jj+1][0], bb[2*jj+1][1],
                        Ks + ((2*jj + b_toff) * 8 + lr) * 136 + kch + b_coff);
            #pragma unroll
            for (int j = 0; j < 8; j++)
                mma_f16(sacc[j], a, bb[j]);
        }

        // ---- softmax on fragments ----
        const bool nm = (j0 + 63 > SPREV + t0);
        float ml0 = -1e30f, ml1 = -1e30f;
        #pragma unroll
        for (int j = 0; j < 8; j++) {
            if (nm) {
                int c0 = j0 + 8 * j + 2 * tg, c1 = c0 + 1;
                sacc[j][0] = (c0 <= qp0) ? sacc[j][0] * scale : -1e30f;
                sacc[j][1] = (c1 <= qp0) ? sacc[j][1] * scale : -1e30f;
                sacc[j][2] = (c0 <= qp1) ? sacc[j][2] * scale : -1e30f;
                sacc[j][3] = (c1 <= qp1) ? sacc[j][3] * scale : -1e30f;
            } else {
                sacc[j][0] *= scale; sacc[j][1] *= scale;
                sacc[j][2] *= scale; sacc[j][3] *= scale;
            }
            ml0 = fmaxf(ml0, fmaxf(sacc[j][0], sacc[j][1]));
            ml1 = fmaxf(ml1, fmaxf(sacc[j][2], sacc[j][3]));
        }
        ml0 = fmaxf(ml0, __shfl_xor_sync(0xffffffffu, ml0, 1));
        ml0 = fmaxf(ml0, __shfl_xor_sync(0xffffffffu, ml0, 2));
        ml1 = fmaxf(ml1, __shfl_xor_sync(0xffffffffu, ml1, 1));
        ml1 = fmaxf(ml1, __shfl_xor_sync(0xffffffffu, ml1, 2));
        float mn0 = fmaxf(m0, ml0), mn1 = fmaxf(m1, ml1);
        float al0 = __expf(m0 - mn0), al1 = __expf(m1 - mn1);

        float ls0 = 0.f, ls1 = 0.f;
        #pragma unroll
        for (int j = 0; j < 8; j++) {
            float p00 = __expf(sacc[j][0] - mn0);
            float p01 = __expf(sacc[j][1] - mn0);
            float p10 = __expf(sacc[j][2] - mn1);
            float p11 = __expf(sacc[j][3] - mn1);
            ls0 += p00 + p01; ls1 += p10 + p11;
            *(__half2*)(PsH + row0       * 72 + 8 * j + 2 * tg) = __floats2half2_rn(p00, p01);
            *(__half2*)(PsH + (row0 + 8) * 72 + 8 * j + 2 * tg) = __floats2half2_rn(p10, p11);
        }
        ls0 += __shfl_xor_sync(0xffffffffu, ls0, 1);
        ls0 += __shfl_xor_sync(0xffffffffu, ls0, 2);
        ls1 += __shfl_xor_sync(0xffffffffu, ls1, 1);
        ls1 += __shfl_xor_sync(0xffffffffu, ls1, 2);
        l0 = l0 * al0 + ls0;  m0 = mn0;
        l1 = l1 * al1 + ls1;  m1 = mn1;

        #pragma unroll
        for (int j = 0; j < 16; j++) {
            oacc[j][0] *= al0; oacc[j][1] *= al0;
            oacc[j][2] *= al1; oacc[j][3] *= al1;
        }
        __syncwarp();   // P rows of this warp: cross-lane STS->LDS visibility

        // ---- O += P V  (fp16; P via ldmatrix, V via ldmatrix.trans) ----
        #pragma unroll
        for (int ks = 0; ks < 4; ks++) {
            const int kch = ks * 16;
            unsigned a[4];
            ldsm_x4(a[0], a[1], a[2], a[3],
                    PsH + (16 * w + a_roff) * 72 + kch + a_coff);
            #pragma unroll
            for (int j2 = 0; j2 < 8; j2++) {
                unsigned r0, r1, r2, r3;
                const __half* vp = Vs + (ks * 16 + vrow_l) * 136 + j2 * 16 + vcol_l;
                ldsm_x4_trans(r0, r1, r2, r3, vp);
                unsigned b0[2] = { r0, r1 };
                unsigned b1[2] = { r2, r3 };
                mma_f16(oacc[2 * j2],     a, b0);
                mma_f16(oacc[2 * j2 + 1], a, b1);
            }
        }
        __syncthreads();
    }

    // epilogue: fp16 ctx (feeds fp16 out-projection A operand)
    float i0 = 1.f / l0, i1 = 1.f / l1;
    __half* c0p = ctxh + ((size_t)(b * TQ_ + t0 + row0)     * H_ + h) * HD_;
    __half* c1p = ctxh + ((size_t)(b * TQ_ + t0 + row0 + 8) * H_ + h) * HD_;
    #pragma unroll
    for (int j = 0; j < 16; j++) {
        int col = 8 * j + 2 * tg;
        *(__half2*)(c0p + col) = __floats2half2_rn(oacc[j][0] * i0, oacc[j][1] * i0);
        *(__half2*)(c1p + col) = __floats2half2_rn(oacc[j][2] * i1, oacc[j][3] * i1);
    }
}

// =============================================================================
// host launcher
// =============================================================================
template<typename T>
static T* sym_addr_t(const void* symbol)
{
    void* p = nullptr;
    cudaGetSymbolAddress(&p, symbol);
    return (T*)p;
}

extern "C" void kernel_launch(void* const* d_in, const int* in_sizes, int n_in,
                              void* d_out, int out_size)
{
    const float* x    = (const float*)d_in[0];
    const float* Wq   = (const float*)d_in[1];
    const float* Wk   = (const float*)d_in[2];
    const float* Wv   = (const float*)d_in[3];
    const float* Wo   = (const float*)d_in[4];
    const float* qw   = (const float*)d_in[5];
    const float* kw   = (const float*)d_in[6];
    const float* cosT = (const float*)d_in[7];
    const float* sinT = (const float*)d_in[8];
    const float* pk   = (const float*)d_in[9];
    const float* pv   = (const float*)d_in[10];
    const int*   pid  = (const int*)d_in[11];
    // d_in[12] = mask, computed analytically

    float* out  = (float*)d_out;                                    // B*T*DIN
    float* kall = out  + (size_t)B_ * TQ_ * DIN_;                   // B*G*SKV*HD
    float* vall = kall + (size_t)B_ * G_ * SKV * HD_;

    __half* wqkvh = sym_addr_t<__half>(g_wqkvh);
    __half* xh    = sym_addr_t<__half>(g_xh);
    __half* woh   = sym_addr_t<__half>(g_woh);
    __half* qh    = sym_addr_t<__half>(g_qh);
    __half* ctxh  = sym_addr_t<__half>(g_ctxh);
    __half* kh    = sym_addr_t<__half>(g_kh);
    __half* vh    = sym_addr_t<__half>(g_vh);

    cudaFuncSetAttribute(gemm_fp16,      cudaFuncAttributeMaxDynamicSharedMemorySize, GEMM_SMEM_H);
    cudaFuncSetAttribute(gemm_qkv_fused, cudaFuncAttributeMaxDynamicSharedMemorySize, GEMM_SMEM_H);
    cudaFuncSetAttribute(attn_tc,        cudaFuncAttributeMaxDynamicSharedMemorySize, ATTN_SMEM);

    // 1) fused fp32 -> fp16 convert pre-pass (x + all weights, one launch)
    to_half_all<<<49152, 256>>>((const float4*)x,  (const float4*)Wq,
                                (const float4*)Wk, (const float4*)Wv,
                                (const float4*)Wo);

    // 2) prev kv cache copy (fp32 outputs + fp16 mirrors)
    prev_scatter<<<2048, 256>>>(pk, pv, kall, vall, kh, vh);

    // 3) fused QKV projection + rmsnorm + rope + scatter
    gemm_qkv_fused<<<dim3(NQKV / 128, BT_ / 128), 128, GEMM_SMEM_H>>>(
        xh, wqkvh, qh, kall, kh, vall, vh, qw, kw, cosT, sinT, pid);

    // 4) attention (full fp16, cp.async KV tiles)
    attn_tc<<<dim3(TQ_ / 128, H_, B_), 256, ATTN_SMEM>>>(qh, kh, vh, ctxh);

    // 5) output projection
    gemm_fp16<<<dim3(DIN_ / 128, BT_ / 128), 128, GEMM_SMEM_H>>>(ctxh, woh, out, BT_, DIN_, DIN_);

    (void)in_sizes; (void)n_in; (void)out_size;
}

// round 17
// speedup vs baseline: 1.1485x; 1.1485x over previous
#include <cuda_runtime.h>
#include <cuda_bf16.h>
#include <cuda_fp16.h>
#include <cstdint>

// Problem constants
#define B_    2
#define TQ_   1024
#define DIN_  4096
#define H_    32
#define G_    8
#define HD_   128
#define SPREV 1024
#define SKV   2048          // SPREV + TQ
#define BT_   (B_*TQ_)      // 2048
#define NQKV  6144          // H*HD + 2*G*HD

// ---------------- scratch (no allocation allowed -> __device__ globals) ---------
__device__ float  g_qkv [(size_t)BT_ * NQKV];        // fused q|k|v projections (fp32)
__device__ __half g_xh  [(size_t)BT_ * DIN_];        // fp16 x
__device__ __half g_wqkvh[(size_t)NQKV * DIN_];      // fp16 [Wq;Wk;Wv]
__device__ __half g_woh [(size_t)DIN_ * H_ * HD_];   // fp16 Wo
__device__ __half g_qh  [(size_t)BT_ * H_ * HD_];    // fp16 Q (post norm+rope, pre-scaled)
__device__ __half g_ctxh[(size_t)BT_ * H_ * HD_];    // fp16 attention output
__device__ __half g_kh  [(size_t)B_ * G_ * SKV * HD_]; // fp16 mirror of k_all
__device__ __half g_vh  [(size_t)B_ * G_ * SKV * HD_]; // fp16 mirror of v_all

// =============================================================================
// helpers
// =============================================================================
__device__ __forceinline__ void cp16(void* s, const void* g){
    unsigned sa = (unsigned)__cvta_generic_to_shared(s);
    asm volatile("cp.async.cg.shared.global [%0], [%1], 16;\n" :: "r"(sa), "l"(g));
}
__device__ __forceinline__ void cp_commit(){ asm volatile("cp.async.commit_group;\n" ::); }
template<int NN> __device__ __forceinline__ void cp_wait(){
    asm volatile("cp.async.wait_group %0;\n" :: "n"(NN));
}
__device__ __forceinline__ void mma_f16(float* c, const unsigned* a, const unsigned* b){
    asm volatile(
      "mma.sync.aligned.m16n8k16.row.col.f32.f16.f16.f32 "
      "{%0,%1,%2,%3}, {%4,%5,%6,%7}, {%8,%9}, {%0,%1,%2,%3};"
      : "+f"(c[0]), "+f"(c[1]), "+f"(c[2]), "+f"(c[3])
      : "r"(a[0]), "r"(a[1]), "r"(a[2]), "r"(a[3]), "r"(b[0]), "r"(b[1]));
}
__device__ __forceinline__ void ldsm_x4(unsigned& r0, unsigned& r1,
                                        unsigned& r2, unsigned& r3,
                                        const void* p){
    unsigned sa = (unsigned)__cvta_generic_to_shared(p);
    asm volatile("ldmatrix.sync.aligned.m8n8.x4.shared.b16 {%0,%1,%2,%3}, [%4];"
                 : "=r"(r0), "=r"(r1), "=r"(r2), "=r"(r3) : "r"(sa));
}
__device__ __forceinline__ void ldsm_x4_trans(unsigned& r0, unsigned& r1,
                                              unsigned& r2, unsigned& r3,
                                              const void* p){
    unsigned sa = (unsigned)__cvta_generic_to_shared(p);
    asm volatile("ldmatrix.sync.aligned.m8n8.x4.trans.shared.b16 {%0,%1,%2,%3}, [%4];"
                 : "=r"(r0), "=r"(r1), "=r"(r2), "=r"(r3) : "r"(sa));
}

// =============================================================================
// fused fp32 -> fp16 convert pre-pass (x, Wq, Wk, Wv, Wo in one launch)
// =============================================================================
__global__ void to_half_all(const float4* __restrict__ x,  const float4* __restrict__ wq,
                            const float4* __restrict__ wk, const float4* __restrict__ wv,
                            const float4* __restrict__ wo)
{
    size_t i = (size_t)blockIdx.x * 256 + threadIdx.x;      // 12,582,912 float4s
    const float4* s; __half* d; size_t off;
    if      (i <  2097152u) { s = x;  d = g_xh;              off = i; }
    else if (i <  6291456u) { s = wq; d = g_wqkvh;           off = i - 2097152u; }
    else if (i <  7340032u) { s = wk; d = g_wqkvh + 16777216; off = i - 6291456u; }
    else if (i <  8388608u) { s = wv; d = g_wqkvh + 20971520; off = i - 7340032u; }
    else                    { s = wo; d = g_woh;             off = i - 8388608u; }
    float4 v = s[off];
    __half2 h0 = __floats2half2_rn(v.x, v.y);
    __half2 h1 = __floats2half2_rn(v.z, v.w);
    uint2 u; u.x = *(unsigned*)&h0; u.y = *(unsigned*)&h1;
    ((uint2*)d)[off] = u;
}

// =============================================================================
// GEMM common: 128x128x64 fp16 mainloop macro bits
// =============================================================================
#define HP 72                        // smem pitch (halves)
#define HBK 64                       // k per stage (halves)
#define GEMM_SMEM_H (2 * 128 * HP * 2 * 2)   // 73728 B

#define GEMM_MAINLOOP(Ag, Bg, K)                                              \
    float c[4][8][4];                                                         \
    _Pragma("unroll")                                                         \
    for (int i = 0; i < 4; i++)                                               \
        _Pragma("unroll")                                                     \
        for (int j = 0; j < 8; j++)                                           \
            _Pragma("unroll")                                                 \
            for (int t = 0; t < 4; t++) c[i][j][t] = 0.f;                     \
    const int nkt = (K) / HBK;                                                \
    HSTAGE(0, 0); cp_commit();                                                \
    const int a_roff = (sel & 1) * 8 + lr;                                    \
    const int a_coff = (sel >> 1) * 8;                                        \
    const int b_toff = (sel >> 1);                                            \
    const int b_coff = (sel & 1) * 8;                                         \
    for (int kt = 0; kt < nkt; kt++) {                                        \
        if (kt + 1 < nkt) { HSTAGE((kt + 1) & 1, kt + 1); cp_commit(); cp_wait<1>(); } \
        else              { cp_wait<0>(); }                                   \
        __syncthreads();                                                      \
        const __half* Ab = As + (kt & 1) * 128 * HP;                          \
        const __half* Bb = Bs + (kt & 1) * 128 * HP;                          \
        _Pragma("unroll")                                                     \
        for (int ks = 0; ks < 4; ks++) {                                      \
            const int kch = ks * 16;                                          \
            unsigned a[4][4], bfr[8][2];                                      \
            _Pragma("unroll")                                                 \
            for (int f = 0; f < 4; f++)                                       \
                ldsm_x4(a[f][0], a[f][1], a[f][2], a[f][3],                   \
                        Ab + (wm + f * 16 + a_roff) * HP + kch + a_coff);     \
            _Pragma("unroll")                                                 \
            for (int jj = 0; jj < 4; jj++)                                    \
                ldsm_x4(bfr[2*jj][0], bfr[2*jj][1], bfr[2*jj+1][0], bfr[2*jj+1][1], \
                        Bb + (wn + (2*jj + b_toff) * 8 + lr) * HP + kch + b_coff);  \
            _Pragma("unroll")                                                 \
            for (int i = 0; i < 4; i++)                                       \
                _Pragma("unroll")                                             \
                for (int j = 0; j < 8; j++)                                   \
                    mma_f16(c[i][j], a[i], bfr[j]);                           \
        }                                                                     \
        __syncthreads();                                                      \
    }

#define HSTAGE(buf, kt) do {                                                 \
    __half* da = As + (buf) * 128 * HP;                                      \
    __half* db = Bs + (buf) * 128 * HP;                                      \
    const __half* sa = Ag + (size_t)(kt) * HBK;                              \
    const __half* sb = Bg + (size_t)(kt) * HBK;                              \
    _Pragma("unroll")                                                        \
    for (int i = 0; i < 8; i++){                                             \
        int idx = i * 128 + tid; int row = idx >> 3; int sg = (idx & 7) * 8; \
        cp16(da + row * HP + sg, sa + (size_t)row * K + sg);                 \
        cp16(db + row * HP + sg, sb + (size_t)row * K + sg);                 \
    }                                                                        \
} while (0)

// =============================================================================
// fp16 tensor-core NT GEMM: C fp32.
// =============================================================================
__global__ void __launch_bounds__(128) gemm_fp16(const __half* __restrict__ A,
                                                 const __half* __restrict__ Bm,
                                                 float* __restrict__ C,
                                                 int M, int N, int K)
{
    extern __shared__ __half shh[];
    __half* As = shh;
    __half* Bs = shh + 2 * 128 * HP;

    const int tid  = threadIdx.x;
    const int lane = tid & 31, warp = tid >> 5;
    const int g  = lane >> 2, tg = lane & 3;
    const int wm = (warp >> 1) * 64, wn = (warp & 1) * 64;
    const int lr  = lane & 7;
    const int sel = lane >> 3;

    const __half* Ag = A  + (size_t)blockIdx.y * 128 * K;
    const __half* Bg = Bm + (size_t)blockIdx.x * 128 * K;

    GEMM_MAINLOOP(Ag, Bg, K)

    #pragma unroll
    for (int i = 0; i < 4; i++) {
        int row0 = blockIdx.y * 128 + wm + i * 16 + g;
        #pragma unroll
        for (int j = 0; j < 8; j++) {
            int col = blockIdx.x * 128 + wn + j * 8 + 2 * tg;
            *(float2*)(C + (size_t)row0 * N + col)       = make_float2(c[i][j][0], c[i][j][1]);
            *(float2*)(C + (size_t)(row0 + 8) * N + col) = make_float2(c[i][j][2], c[i][j][3]);
        }
    }
}

// =============================================================================
// Per-head RMSNorm + RoPE core.  One warp per head; lane l owns dims
// {l, l+32, l+64, l+96}.  cos/sin reads are lane-coalesced.
// =============================================================================
__device__ __forceinline__ void norm_rope_core(const float* __restrict__ inp,
                                               const float* __restrict__ w,
                                               const float* __restrict__ cosT,
                                               const float* __restrict__ sinT,
                                               int pos, int l,
                                               float& o0, float& o1, float& o2, float& o3)
{
    float v0 = inp[l], v1 = inp[l + 32], v2 = inp[l + 64], v3 = inp[l + 96];
    float ss = v0 * v0 + v1 * v1 + v2 * v2 + v3 * v3;
    #pragma unroll
    for (int off = 16; off; off >>= 1) ss += __shfl_xor_sync(0xffffffffu, ss, off);
    float rinv = rsqrtf(ss * (1.f / 128.f) + 1e-6f);
    v0 *= rinv * w[l];      v1 *= rinv * w[l + 32];
    v2 *= rinv * w[l + 64]; v3 *= rinv * w[l + 96];
    const float* c = cosT + (size_t)pos * 128;
    const float* s = sinT + (size_t)pos * 128;
    o0 = v0 * c[l]      - v2 * s[l];
    o1 = v1 * c[l + 32] - v3 * s[l + 32];
    o2 = v2 * c[l + 64] + v0 * s[l + 64];
    o3 = v3 * c[l + 96] + v1 * s[l + 96];
}

// Q: fp32 qkv (row stride NQKV) -> fp16 g_qh, PRE-SCALED by 1/sqrt(HD)
__global__ void q_norm_rope(const float* __restrict__ qkv, __half* __restrict__ qh,
                            const float* __restrict__ w,
                            const float* __restrict__ cosT, const float* __restrict__ sinT,
                            const int* __restrict__ pid)
{
    const float scale = 0.08838834764831845f;    // 1/sqrt(128)
    int bt = blockIdx.x;
    int h  = threadIdx.x >> 5;
    int l  = threadIdx.x & 31;
    const float* base = qkv + (size_t)bt * NQKV + h * HD_;
    float o0, o1, o2, o3;
    norm_rope_core(base, w, cosT, sinT, pid[bt], l, o0, o1, o2, o3);
    __half* ob = qh + (size_t)bt * (H_ * HD_) + h * HD_;
    ob[l]      = __float2half_rn(o0 * scale);
    ob[l + 32] = __float2half_rn(o1 * scale);
    ob[l + 64] = __float2half_rn(o2 * scale);
    ob[l + 96] = __float2half_rn(o3 * scale);
}

// K: qkv cols [4096,5120) -> exact fp32 kall (output) + fp16 mirror
__global__ void k_norm_rope_scatter(const float* __restrict__ qkv,
                                    float* __restrict__ kall,
                                    __half* __restrict__ kh,
                                    const float* __restrict__ w,
                                    const float* __restrict__ cosT,
                                    const float* __restrict__ sinT,
                                    const int* __restrict__ pid)
{
    int bt = blockIdx.x;
    int b = bt >> 10, t = bt & 1023;
    int g = threadIdx.x >> 5;
    int l = threadIdx.x & 31;
    const float* src = qkv + (size_t)bt * NQKV + H_ * HD_ + g * HD_;
    size_t ro = (((size_t)(b * G_ + g) * SKV) + SPREV + t) * HD_;
    float o0, o1, o2, o3;
    norm_rope_core(src, w, cosT, sinT, pid[bt], l, o0, o1, o2, o3);
    float* dst = kall + ro;
    dst[l] = o0; dst[l + 32] = o1; dst[l + 64] = o2; dst[l + 96] = o3;
    __half* dh = kh + ro;
    dh[l]      = __float2half_rn(o0);
    dh[l + 32] = __float2half_rn(o1);
    dh[l + 64] = __float2half_rn(o2);
    dh[l + 96] = __float2half_rn(o3);
}

// V in qkv cols [5120, 6144) -> fp32 v_all + fp16 mirror
__global__ void v_scatter(const float* __restrict__ qkv, float* __restrict__ vall,
                          __half* __restrict__ vh)
{
    size_t i = (size_t)blockIdx.x * blockDim.x + threadIdx.x;  // 524288 float4s
    int d4 = i & 31;
    int g  = (i >> 5) & 7;
    int bt = (int)(i >> 8);
    int b = bt >> 10, t = bt & 1023;
    size_t src = (size_t)bt * (NQKV / 4) + (H_ * HD_ + G_ * HD_) / 4 + g * 32 + d4;
    size_t dst = (((size_t)(b * G_ + g) * SKV) + SPREV + t) * 32 + d4;
    float4 v = ((const float4*)qkv)[src];
    ((float4*)vall)[dst] = v;
    __half2 h0 = __floats2half2_rn(v.x, v.y);
    __half2 h1 = __floats2half2_rn(v.z, v.w);
    uint2 u; u.x = *(unsigned*)&h0; u.y = *(unsigned*)&h1;
    ((uint2*)vh)[dst] = u;
}

// prev_k/prev_v -> fp32 caches + fp16 mirrors
__global__ void prev_scatter(const float* __restrict__ pk, const float* __restrict__ pv,
                             float* __restrict__ kall, float* __restrict__ vall,
                             __half* __restrict__ kh, __half* __restrict__ vh)
{
    size_t i = (size_t)blockIdx.x * blockDim.x + threadIdx.x;  // 524288 float4s
    int d4 = i & 31;
    int s  = (i >> 5) & 1023;
    int bg = (int)(i >> 15);
    size_t dst = ((size_t)bg * SKV + s) * 32 + d4;
    float4 k = ((const float4*)pk)[i];
    float4 v = ((const float4*)pv)[i];
    ((float4*)kall)[dst] = k;
    ((float4*)vall)[dst] = v;
    __half2 a0 = __floats2half2_rn(k.x, k.y), a1 = __floats2half2_rn(k.z, k.w);
    __half2 b0 = __floats2half2_rn(v.x, v.y), b1 = __floats2half2_rn(v.z, v.w);
    uint2 uk; uk.x = *(unsigned*)&a0; uk.y = *(unsigned*)&a1;
    uint2 uv; uv.x = *(unsigned*)&b0; uv.y = *(unsigned*)&b1;
    ((uint2*)kh)[dst] = uk;
    ((uint2*)vh)[dst] = uv;
}

// =============================================================================
// Full-fp16 tensor-core flash attention (m16n8k16, fp32 accum), software-
// pipelined: next K tile prefetched into Ks (single buffer, reloaded after the
// S-phase barrier), next V tile into double-buffered Vs — both overlap
// softmax+PV. Q pre-scaled by 1/sqrt(HD) upstream.
// Block 256 threads (8 warps) = (b, h, 128-query tile); KV tile = 64.
// Smem (half): Qs 128x136, Ks 64x136, Vs 2x 64x136, Ps 128x72.
// Total 105472 B -> still 2 CTAs/SM.
// =============================================================================
#define ATTN_SMEM 105472

__global__ void __launch_bounds__(256, 2) attn_tc(const __half* __restrict__ qh,
                                                  const __half* __restrict__ kh,
                                                  const __half* __restrict__ vh,
                                                  __half* __restrict__ ctxh)
{
    extern __shared__ char smraw[];
    __half* Qs  = (__half*)smraw;                     // 128 x 136
    __half* Ks  = (__half*)(smraw + 34816);           // 64 x 136
    __half* Vs0 = (__half*)(smraw + 52224);           // 64 x 136 (buffer 0)
    __half* Vs1 = (__half*)(smraw + 69632);           // 64 x 136 (buffer 1)
    __half* PsH = (__half*)(smraw + 87040);           // 128 x 72

    const int t0 = blockIdx.x * 128;
    const int h  = blockIdx.y;
    const int b  = blockIdx.z;
    const int gk = h >> 2;             // kv group (H/G = 4)
    const int tid = threadIdx.x;
    const int lane = tid & 31, w = tid >> 5;
    const int g = lane >> 2, tg = lane & 3;
    const int lr  = lane & 7;
    const int sel = lane >> 3;

    // Q tile (fp16, rows stride H*HD)
    const __half* qbase = qh + (size_t)(b * TQ_ + t0) * (H_ * HD_) + h * HD_;
    #pragma unroll 4
    for (int i = tid; i < 128 * 16; i += 256) {
        int row = i >> 4, c8 = (i & 15) * 8;
        *(uint4*)(Qs + row * 136 + c8) =
            *(const uint4*)(qbase + (size_t)row * (H_ * HD_) + c8);
    }

    const int row0 = 16 * w + g;
    const int qp0 = SPREV + t0 + row0;
    const int qp1 = qp0 + 8;
    const int kv_lim = SPREV + t0 + 128;

    const int a_roff = (sel & 1) * 8 + lr;
    const int a_coff = (sel >> 1) * 8;
    const int b_toff = (sel >> 1);
    const int b_coff = (sel & 1) * 8;
    const int vrow_l = lane & 15;
    const int vcol_l = (lane >> 4) << 3;

    const __half* kb = kh + (size_t)(b * G_ + gk) * SKV * HD_;
    const __half* vb = vh + (size_t)(b * G_ + gk) * SKV * HD_;

    float oacc[16][4];
    #pragma unroll
    for (int j = 0; j < 16; j++)
        #pragma unroll
        for (int t = 0; t < 4; t++) oacc[j][t] = 0.f;
    float m0 = -1e30f, m1 = -1e30f, l0 = 0.f, l1 = 0.f;

    // prologue: load K0 -> Ks, V0 -> Vs0
    #pragma unroll
    for (int i = tid; i < 64 * 16; i += 256) {
        int row = i >> 4, sg = (i & 15) * 8;
        cp16(Ks  + row * 136 + sg, kb + (size_t)row * HD_ + sg);
        cp16(Vs0 + row * 136 + sg, vb + (size_t)row * HD_ + sg);
    }
    cp_commit();
    cp_wait<0>();
    __syncthreads();

    for (int j0 = 0; j0 < kv_lim; j0 += 64) {
        __half* Vcur = ((j0 >> 6) & 1) ? Vs1 : Vs0;
        __half* Vnxt = ((j0 >> 6) & 1) ? Vs0 : Vs1;
        const bool more = (j0 + 64 < kv_lim);

        // ---- S = Q K^T  (fp16 m16n8k16, 8 k-steps, ldmatrix frags) ----
        float sacc[8][4];
        #pragma unroll
        for (int j = 0; j < 8; j++)
            #pragma unroll
            for (int t = 0; t < 4; t++) sacc[j][t] = 0.f;

        #pragma unroll
        for (int ks = 0; ks < 8; ks++) {
            const int kch = ks * 16;
            unsigned a[4];
            ldsm_x4(a[0], a[1], a[2], a[3],
                    Qs + (16 * w + a_roff) * 136 + kch + a_coff);
            unsigned bb[8][2];
            #pragma unroll
            for (int jj = 0; jj < 4; jj++)
                ldsm_x4(bb[2*jj][0], bb[2*jj][1], bb[2*jj+1][0], bb[2*jj+1][1],
                        Ks + ((2*jj + b_toff) * 8 + lr) * 136 + kch + b_coff);
            #pragma unroll
            for (int j = 0; j < 8; j++)
                mma_f16(sacc[j], a, bb[j]);
        }
        __syncthreads();            // all warps done reading Ks

        // prefetch next K -> Ks, next V -> Vnxt (overlaps softmax + PV)
        if (more) {
            #pragma unroll
            for (int i = tid; i < 64 * 16; i += 256) {
                int row = i >> 4, sg = (i & 15) * 8;
                cp16(Ks   + row * 136 + sg, kb + (size_t)(j0 + 64 + row) * HD_ + sg);
                cp16(Vnxt + row * 136 + sg, vb + (size_t)(j0 + 64 + row) * HD_ + sg);
            }
            cp_commit();
        }

        // ---- softmax on fragments (Q pre-scaled; no scale multiply) ----
        const bool nm = (j0 + 63 > SPREV + t0);
        float ml0 = -1e30f, ml1 = -1e30f;
        #pragma unroll
        for (int j = 0; j < 8; j++) {
            if (nm) {
                int c0 = j0 + 8 * j + 2 * tg, c1 = c0 + 1;
                if (c0 > qp0) sacc[j][0] = -1e30f;
                if (c1 > qp0) sacc[j][1] = -1e30f;
                if (c0 > qp1) sacc[j][2] = -1e30f;
                if (c1 > qp1) sacc[j][3] = -1e30f;
            }
            ml0 = fmaxf(ml0, fmaxf(sacc[j][0], sacc[j][1]));
            ml1 = fmaxf(ml1, fmaxf(sacc[j][2], sacc[j][3]));
        }
        ml0 = fmaxf(ml0, __shfl_xor_sync(0xffffffffu, ml0, 1));
        ml0 = fmaxf(ml0, __shfl_xor_sync(0xffffffffu, ml0, 2));
        ml1 = fmaxf(ml1, __shfl_xor_sync(0xffffffffu, ml1, 1));
        ml1 = fmaxf(ml1, __shfl_xor_sync(0xffffffffu, ml1, 2));
        float mn0 = fmaxf(m0, ml0), mn1 = fmaxf(m1, ml1);
        float al0 = __expf(m0 - mn0), al1 = __expf(m1 - mn1);

        float ls0 = 0.f, ls1 = 0.f;
        #pragma unroll
        for (int j = 0; j < 8; j++) {
            float p00 = __expf(sacc[j][0] - mn0);
            float p01 = __expf(sacc[j][1] - mn0);
            float p10 = __expf(sacc[j][2] - mn1);
            float p11 = __expf(sacc[j][3] - mn1);
            ls0 += p00 + p01; ls1 += p10 + p11;
            *(__half2*)(PsH + row0       * 72 + 8 * j + 2 * tg) = __floats2half2_rn(p00, p01);
            *(__half2*)(PsH + (row0 + 8) * 72 + 8 * j + 2 * tg) = __floats2half2_rn(p10, p11);
        }
        ls0 += __shfl_xor_sync(0xffffffffu, ls0, 1);
        ls0 += __shfl_xor_sync(0xffffffffu, ls0, 2);
        ls1 += __shfl_xor_sync(0xffffffffu, ls1, 1);
        ls1 += __shfl_xor_sync(0xffffffffu, ls1, 2);
        l0 = l0 * al0 + ls0;  m0 = mn0;
        l1 = l1 * al1 + ls1;  m1 = mn1;

        #pragma unroll
        for (int j = 0; j < 16; j++) {
            oacc[j][0] *= al0; oacc[j][1] *= al0;
            oacc[j][2] *= al1; oacc[j][3] *= al1;
        }
        __syncwarp();   // P rows of this warp: cross-lane STS->LDS visibility

        // ---- O += P V  (fp16; P via ldmatrix, V via ldmatrix.trans) ----
        #pragma unroll
        for (int ks = 0; ks < 4; ks++) {
            const int kch = ks * 16;
            unsigned a[4];
            ldsm_x4(a[0], a[1], a[2], a[3],
                    PsH + (16 * w + a_roff) * 72 + kch + a_coff);
            #pragma unroll
            for (int j2 = 0; j2 < 8; j2++) {
                unsigned r0, r1, r2, r3;
                const __half* vp = Vcur + (ks * 16 + vrow_l) * 136 + j2 * 16 + vcol_l;
                ldsm_x4_trans(r0, r1, r2, r3, vp);
                unsigned b0[2] = { r0, r1 };
                unsigned b1[2] = { r2, r3 };
                mma_f16(oacc[2 * j2],     a, b0);
                mma_f16(oacc[2 * j2 + 1], a, b1);
            }
        }

        if (more) cp_wait<0>();     // prefetch should be long done
        __syncthreads();            // Ps free, new Ks/Vnxt visible to all
    }

    // epilogue: fp16 ctx (feeds fp16 out-projection A operand)
    float i0 = 1.f / l0, i1 = 1.f / l1;
    __half* c0p = ctxh + ((size_t)(b * TQ_ + t0 + row0)     * H_ + h) * HD_;
    __half* c1p = ctxh + ((size_t)(b * TQ_ + t0 + row0 + 8) * H_ + h) * HD_;
    #pragma unroll
    for (int j = 0; j < 16; j++) {
        int col = 8 * j + 2 * tg;
        *(__half2*)(c0p + col) = __floats2half2_rn(oacc[j][0] * i0, oacc[j][1] * i0);
        *(__half2*)(c1p + col) = __floats2half2_rn(oacc[j][2] * i1, oacc[j][3] * i1);
    }
}

// =============================================================================
// host launcher
// =============================================================================
template<typename T>
static T* sym_addr_t(const void* symbol)
{
    void* p = nullptr;
    cudaGetSymbolAddress(&p, symbol);
    return (T*)p;
}

extern "C" void kernel_launch(void* const* d_in, const int* in_sizes, int n_in,
                              void* d_out, int out_size)
{
    const float* x    = (const float*)d_in[0];
    const float* Wq   = (const float*)d_in[1];
    const float* Wk   = (const float*)d_in[2];
    const float* Wv   = (const float*)d_in[3];
    const float* Wo   = (const float*)d_in[4];
    const float* qw   = (const float*)d_in[5];
    const float* kw   = (const float*)d_in[6];
    const float* cosT = (const float*)d_in[7];
    const float* sinT = (const float*)d_in[8];
    const float* pk   = (const float*)d_in[9];
    const float* pv   = (const float*)d_in[10];
    const int*   pid  = (const int*)d_in[11];
    // d_in[12] = mask, computed analytically

    float* out  = (float*)d_out;                                    // B*T*DIN
    float* kall = out  + (size_t)B_ * TQ_ * DIN_;                   // B*G*SKV*HD
    float* vall = kall + (size_t)B_ * G_ * SKV * HD_;

    float*  qkv   = sym_addr_t<float>(g_qkv);
    __half* wqkvh = sym_addr_t<__half>(g_wqkvh);
    __half* xh    = sym_addr_t<__half>(g_xh);
    __half* woh   = sym_addr_t<__half>(g_woh);
    __half* qh    = sym_addr_t<__half>(g_qh);
    __half* ctxh  = sym_addr_t<__half>(g_ctxh);
    __half* kh    = sym_addr_t<__half>(g_kh);
    __half* vh    = sym_addr_t<__half>(g_vh);

    cudaFuncSetAttribute(gemm_fp16, cudaFuncAttributeMaxDynamicSharedMemorySize, GEMM_SMEM_H);
    cudaFuncSetAttribute(attn_tc,   cudaFuncAttributeMaxDynamicSharedMemorySize, ATTN_SMEM);

    // 1) fused fp32 -> fp16 convert pre-pass (x + all weights, one launch)
    to_half_all<<<49152, 256>>>((const float4*)x,  (const float4*)Wq,
                                (const float4*)Wk, (const float4*)Wv,
                                (const float4*)Wo);

    // 2) fused QKV projection: [2048 x 6144] = xh @ [Wq;Wk;Wv]^T  (fp32 out)
    gemm_fp16<<<dim3(NQKV / 128, BT_ / 128), 128, GEMM_SMEM_H>>>(xh, wqkvh, qkv, BT_, NQKV, DIN_);

    // 3) prev kv cache copy (fp32 outputs + fp16 mirrors)
    prev_scatter<<<2048, 256>>>(pk, pv, kall, vall, kh, vh);

    // 4-6) norm + rope + kv assembly (dual-precision writes)
    q_norm_rope<<<BT_, H_ * 32>>>(qkv, qh, qw, cosT, sinT, pid);
    k_norm_rope_scatter<<<BT_, G_ * 32>>>(qkv, kall, kh, kw, cosT, sinT, pid);
    v_scatter<<<2048, 256>>>(qkv, vall, vh);

    // 7) attention (full fp16, software-pipelined KV prefetch)
    attn_tc<<<dim3(TQ_ / 128, H_, B_), 256, ATTN_SMEM>>>(qh, kh, vh, ctxh);

    // 8) output projection
    gemm_fp16<<<dim3(DIN_ / 128, BT_ / 128), 128, GEMM_SMEM_H>>>(ctxh, woh, out, BT_, DIN_, DIN_);

    (void)in_sizes; (void)n_in; (void)out_size;
}